// round 15
// baseline (speedup 1.0000x reference)
#include <cuda_runtime.h>
#include <cuda_fp16.h>
#include <cstdint>

// =====================================================================
// Fused LayerNorm -> Linear -> exact GELU -> residual
//   x [M=32768, D=2048] fp32, W [D, H=2048] fp32, out [M, H] fp32
// R14: crossbar-relief GEMM. smem crossbar was co-saturated with the
//      tensor pipe (256 B/HMMA vs 256 B/HMMA budget). Warp tile 64x64,
//      BM=128 BN=256 (8 warps, 2x4) cuts LDSM traffic to 176 B/HMMA so
//      the tensor pipe binds alone. occ=1, 255-reg budget, ks-prefetch.
//   D = A_fp16 * B_fp16 (fp32 accumulate), rel_err ~1.7e-4.
// =====================================================================

#define LN_EPS 1e-5f
static constexpr int MROWS = 32768;
static constexpr int DDIM  = 2048;

__device__ __align__(1024) __half g_A[(size_t)MROWS * DDIM];   // LN(x) fp16
__device__ __align__(1024) __half g_B[(size_t)DDIM * DDIM];    // W^T fp16 [N,K]

// ------------------------- helpers ----------------------------------
__device__ __forceinline__ uint32_t smem_u32(const void* p) {
    uint32_t a;
    asm("{ .reg .u64 t; cvta.to.shared.u64 t, %1; cvt.u32.u64 %0, t; }"
        : "=r"(a) : "l"(p));
    return a;
}
__device__ __forceinline__ uint32_t swz(uint32_t off) {   // SW128: bits[6:4] ^= bits[9:7]
    return off ^ ((off >> 3) & 0x70u);
}
__device__ __forceinline__ void cp16(uint32_t dst, const void* src) {
    asm volatile("cp.async.cg.shared.global [%0], [%1], 16;" :: "r"(dst), "l"(src));
}
__device__ __forceinline__ void ldsm4(uint32_t* r, uint32_t a) {
    asm volatile("ldmatrix.sync.aligned.m8n8.x4.shared.b16 {%0,%1,%2,%3}, [%4];"
        : "=r"(r[0]), "=r"(r[1]), "=r"(r[2]), "=r"(r[3]) : "r"(a));
}
__device__ __forceinline__ void mma16816(float* c, const uint32_t* a, const uint32_t* b) {
    asm volatile(
        "mma.sync.aligned.m16n8k16.row.col.f32.f16.f16.f32 "
        "{%0,%1,%2,%3}, {%4,%5,%6,%7}, {%8,%9}, {%0,%1,%2,%3};"
        : "+f"(c[0]), "+f"(c[1]), "+f"(c[2]), "+f"(c[3])
        : "r"(a[0]), "r"(a[1]), "r"(a[2]), "r"(a[3]), "r"(b[0]), "r"(b[1]));
}

// --------- Stage 1+2 merged: LN (warp/row) and W transpose ----------
__global__ __launch_bounds__(256)
void prep_kernel(const float* __restrict__ x,
                 const float* __restrict__ gamma,
                 const float* __restrict__ beta,
                 const float* __restrict__ W,
                 int D, int N, int lnBlocks) {
    if (blockIdx.x < (unsigned)lnBlocks) {
        const int wid  = threadIdx.x >> 5;
        const int lane = threadIdx.x & 31;
        const int row  = blockIdx.x * 8 + wid;
        const float* xr = x + (size_t)row * D;

        float4 v[16];
        #pragma unroll
        for (int i = 0; i < 16; i++)
            v[i] = *reinterpret_cast<const float4*>(xr + (i * 32 + lane) * 4);

        float s = 0.f, s2 = 0.f;
        #pragma unroll
        for (int i = 0; i < 16; i++) {
            s  += v[i].x + v[i].y + v[i].z + v[i].w;
            s2 += v[i].x * v[i].x + v[i].y * v[i].y
                + v[i].z * v[i].z + v[i].w * v[i].w;
        }
        #pragma unroll
        for (int o = 16; o > 0; o >>= 1) {
            s  += __shfl_xor_sync(0xFFFFFFFFu, s, o);
            s2 += __shfl_xor_sync(0xFFFFFFFFu, s2, o);
        }
        const float mu = s / (float)D;
        const float rs = rsqrtf(s2 / (float)D - mu * mu + LN_EPS);

        __half* arow = g_A + (size_t)row * D;
        #pragma unroll
        for (int i = 0; i < 16; i++) {
            const int c = (i * 32 + lane) * 4;
            const float4 g4 = *reinterpret_cast<const float4*>(gamma + c);
            const float4 b4 = *reinterpret_cast<const float4*>(beta  + c);
            union { __half h[4]; uint2 u; } o;
            o.h[0] = __float2half((v[i].x - mu) * rs * g4.x + b4.x);
            o.h[1] = __float2half((v[i].y - mu) * rs * g4.y + b4.y);
            o.h[2] = __float2half((v[i].z - mu) * rs * g4.z + b4.z);
            o.h[3] = __float2half((v[i].w - mu) * rs * g4.w + b4.w);
            *reinterpret_cast<uint2*>(arow + c) = o.u;
        }
    } else {
        __shared__ float tile[32][33];
        const int b  = blockIdx.x - lnBlocks;
        const int n0 = (b & (N / 32 - 1)) * 32;
        const int k0 = (b / (N / 32)) * 32;
        const int tx = threadIdx.x & 31, ty = threadIdx.x >> 5;  // 32 x 8
        #pragma unroll
        for (int r = 0; r < 32; r += 8)
            tile[ty + r][tx] = W[(size_t)(k0 + ty + r) * N + n0 + tx];
        __syncthreads();
        #pragma unroll
        for (int r = 0; r < 32; r += 8) {
            const int n = n0 + ty + r, k = k0 + tx;
            g_B[(size_t)n * D + k] = __float2half(tile[tx][ty + r]);
        }
    }
}

// ------------------------- Stage 3: GEMM ----------------------------
static constexpr int BM = 128, BN = 256, BK = 64;
static constexpr int THREADS = 256;
static constexpr int STAGES = 3;
// per-stage (128B rows): A [0,16K) B [16K,48K)
static constexpr int B_OFF       = 16384;
static constexpr int STAGE_BYTES = 49152;
static constexpr int SMEM_TOTAL  = 1024 + STAGES * STAGE_BYTES;  // 148480

__global__ __launch_bounds__(THREADS, 1)
void ffn_mma_kernel(const float* __restrict__ x,
                    const float* __restrict__ bias,
                    float* __restrict__ out,
                    int K, int H) {
    extern __shared__ __align__(1024) uint8_t dynsmem[];
    uint32_t sb = smem_u32(dynsmem);
    sb = (sb + 1023) & ~1023u;

    const int t    = threadIdx.x;
    const int lane = t & 31;
    const int wid  = t >> 5;
    const int g    = lane >> 2;
    const int tg   = lane & 3;
    const int m0   = blockIdx.y * BM;
    const int n0   = blockIdx.x * BN;
    const int wm   = (wid >> 2) * 64;   // 0 or 64
    const int wn   = (wid & 3)  * 64;   // 0..192  (warp tile 64x64)

    // ---- cp.async: 128B rows, 8 x 16B chunks/row; 4 A + 8 B per thread
    const int ldrow = t >> 3;            // 0..31
    const int ldc   = t & 7;
    const size_t aoff = (size_t)(m0 + ldrow) * K + ldc * 8;
    const size_t boff = (size_t)(n0 + ldrow) * K + ldc * 8;
    const __half* pA = g_A + aoff;
    const __half* pB = g_B + boff;
    const size_t rstep = (size_t)32 * K;

    const uint32_t dstA = sb + swz((uint32_t)(ldrow * 128 + ldc * 16));
    const uint32_t dstB = sb + B_OFF + swz((uint32_t)(ldrow * 128 + ldc * 16));

    // ---- ldmatrix base addresses (stage 0, ks=0) ----
    const int matid = lane >> 3, r8 = lane & 7;
    uint32_t aAdr[4], bAdr[4];
    #pragma unroll
    for (int mt = 0; mt < 4; mt++) {
        const uint32_t m = wm + mt * 16 + (matid & 1) * 8 + r8;
        aAdr[mt] = sb + swz(m * 128 + (matid >> 1) * 16);
    }
    #pragma unroll
    for (int p = 0; p < 4; p++) {
        const uint32_t n = wn + p * 16 + (matid >> 1) * 8 + r8;
        bAdr[p] = sb + B_OFF + swz(n * 128 + (matid & 1) * 16);
    }

    float acc[4][8][4];
    #pragma unroll
    for (int mt = 0; mt < 4; mt++)
        #pragma unroll
        for (int nt = 0; nt < 8; nt++)
            #pragma unroll
            for (int r = 0; r < 4; r++) acc[mt][nt][r] = 0.f;

    const int NT = K / BK;   // 32

    auto load_stage = [&](int kt, uint32_t so) {
        const int kc = kt * BK;
        const __half* a = pA + kc;
        const __half* b = pB + kc;
        #pragma unroll
        for (int i = 0; i < 4; i++)
            cp16(dstA + so + i * 4096, a + i * rstep);
        #pragma unroll
        for (int i = 0; i < 8; i++)
            cp16(dstB + so + i * 4096, b + i * rstep);
    };

    load_stage(0, 0);
    asm volatile("cp.async.commit_group;" ::: "memory");
    load_stage(1, STAGE_BYTES);
    asm volatile("cp.async.commit_group;" ::: "memory");

    int cur = 0, nxt2 = 2;

    uint32_t ah[2][4][4], bh[2][16];   // ks double-buffered fragments

    for (int kt = 0; kt < NT; kt++) {
        asm volatile("cp.async.wait_group 1;" ::: "memory");
        __syncthreads();

        if (kt + 2 < NT) load_stage(kt + 2, nxt2 * STAGE_BYTES);
        asm volatile("cp.async.commit_group;" ::: "memory");

        const uint32_t so = cur * STAGE_BYTES;

        // ks=0 fragments
        #pragma unroll
        for (int p = 0; p < 4; p++)
            ldsm4(&bh[0][p * 4], bAdr[p] + so);
        #pragma unroll
        for (int mt = 0; mt < 4; mt++)
            ldsm4(ah[0][mt], aAdr[mt] + so);

        #pragma unroll
        for (int ks = 0; ks < 4; ks++) {
            const int cf = ks & 1, nf = cf ^ 1;
            if (ks < 3) {   // prefetch ks+1 fragments before this ks's MMAs
                const uint32_t kx = (ks + 1) * 32;
                #pragma unroll
                for (int p = 0; p < 4; p++)
                    ldsm4(&bh[nf][p * 4], (bAdr[p] + so) ^ kx);
                #pragma unroll
                for (int mt = 0; mt < 4; mt++)
                    ldsm4(ah[nf][mt], (aAdr[mt] + so) ^ kx);
            }
            #pragma unroll
            for (int mt = 0; mt < 4; mt++)
                #pragma unroll
                for (int nt = 0; nt < 8; nt++)
                    mma16816(acc[mt][nt], ah[cf][mt], &bh[cf][nt * 2]);
        }

        cur  = (cur  == 2) ? 0 : cur  + 1;
        nxt2 = (nxt2 == 2) ? 0 : nxt2 + 1;
    }

    // ---- epilogue: bias + exact GELU + residual ----
    #pragma unroll
    for (int mt = 0; mt < 4; mt++) {
        #pragma unroll
        for (int half = 0; half < 2; half++) {
            const int m = m0 + wm + mt * 16 + g + half * 8;
            const float* xr = x + (size_t)m * H;
            float* orow = out + (size_t)m * H;
            #pragma unroll
            for (int nt = 0; nt < 8; nt++) {
                const int n = n0 + wn + nt * 8 + tg * 2;
                float c0 = acc[mt][nt][half * 2 + 0];
                float c1 = acc[mt][nt][half * 2 + 1];
                const float2 bb = *reinterpret_cast<const float2*>(bias + n);
                float h0 = c0 + bb.x, h1 = c1 + bb.y;
                h0 = 0.5f * h0 * (1.0f + erff(h0 * 0.70710678118654752f));
                h1 = 0.5f * h1 * (1.0f + erff(h1 * 0.70710678118654752f));
                const float2 xv = *reinterpret_cast<const float2*>(xr + n);
                float2 o;
                o.x = h0 + xv.x;
                o.y = h1 + xv.y;
                *reinterpret_cast<float2*>(orow + n) = o;
            }
        }
    }
}

// ------------------------- host side ---------------------------------
extern "C" void kernel_launch(void* const* d_in, const int* in_sizes, int n_in,
                              void* d_out, int out_size) {
    const float* x     = (const float*)d_in[0];
    const float* gamma = (const float*)d_in[1];
    const float* beta  = (const float*)d_in[2];
    const float* W     = (const float*)d_in[3];
    const float* bias  = (const float*)d_in[4];
    float* out = (float*)d_out;

    const int D = in_sizes[1];
    const int H = in_sizes[4];
    const int M = in_sizes[0] / D;

    const int lnBlocks = M / 8;
    const int wBlocks  = (D / 32) * (H / 32);
    prep_kernel<<<lnBlocks + wBlocks, 256>>>(x, gamma, beta, W, D, H, lnBlocks);

    cudaFuncSetAttribute(ffn_mma_kernel,
                         cudaFuncAttributeMaxDynamicSharedMemorySize, SMEM_TOTAL);
    dim3 ggrid(H / BN, M / BM);
    ffn_mma_kernel<<<ggrid, THREADS, SMEM_TOTAL>>>(x, bias, out, D, H);
}

// round 16
// speedup vs baseline: 1.0694x; 1.0694x over previous
#include <cuda_runtime.h>
#include <cuda_fp16.h>
#include <cstdint>

// =====================================================================
// Fused LayerNorm -> Linear -> exact GELU -> residual
//   x [M=32768, D=2048] fp32, W [D, H=2048] fp32, out [M, H] fp32
// R15: SINGLE fused kernel. Grid = [wsplit | {16 LN + 16 GEMM} x 256].
//   GEMM blocks spin on flags set by their LN row-block / wsplit column
//   group; dependencies always precede in blockIdx order (no deadlock).
//   GEMM inner loop identical to R11 (best known: tensor ~64% ceiling).
//   D = A_fp16 * B_fp16 (fp32 accumulate), rel_err ~1.7e-4.
// =====================================================================

#define LN_EPS 1e-5f
static constexpr int MROWS = 32768;
static constexpr int DDIM  = 2048;

__device__ __align__(1024) __half g_A[(size_t)MROWS * DDIM];   // LN(x) fp16
__device__ __align__(1024) __half g_B[(size_t)DDIM * DDIM];    // W^T fp16 [N,K]
// flags: [0,256) per-128-row LN groups (target 16); [256,272) per-bx B groups (target 256)
__device__ int g_flags[272];

// ------------------------- helpers ----------------------------------
__device__ __forceinline__ uint32_t smem_u32(const void* p) {
    uint32_t a;
    asm("{ .reg .u64 t; cvta.to.shared.u64 t, %1; cvt.u32.u64 %0, t; }"
        : "=r"(a) : "l"(p));
    return a;
}
__device__ __forceinline__ uint32_t swz(uint32_t off) {   // SW128: bits[6:4] ^= bits[9:7]
    return off ^ ((off >> 3) & 0x70u);
}
__device__ __forceinline__ void cp16(uint32_t dst, const void* src) {
    asm volatile("cp.async.cg.shared.global [%0], [%1], 16;" :: "r"(dst), "l"(src));
}
__device__ __forceinline__ void ldsm4(uint32_t* r, uint32_t a) {
    asm volatile("ldmatrix.sync.aligned.m8n8.x4.shared.b16 {%0,%1,%2,%3}, [%4];"
        : "=r"(r[0]), "=r"(r[1]), "=r"(r[2]), "=r"(r[3]) : "r"(a));
}
__device__ __forceinline__ void mma16816(float* c, const uint32_t* a, const uint32_t* b) {
    asm volatile(
        "mma.sync.aligned.m16n8k16.row.col.f32.f16.f16.f32 "
        "{%0,%1,%2,%3}, {%4,%5,%6,%7}, {%8,%9}, {%0,%1,%2,%3};"
        : "+f"(c[0]), "+f"(c[1]), "+f"(c[2]), "+f"(c[3])
        : "r"(a[0]), "r"(a[1]), "r"(a[2]), "r"(a[3]), "r"(b[0]), "r"(b[1]));
}

// ------------------------- flag reset --------------------------------
__global__ void zero_flags_kernel() {
    if (threadIdx.x < 272) g_flags[threadIdx.x] = 0;
}

// ------------------------- fused kernel ------------------------------
static constexpr int BM = 128, BN = 128, BK = 64;
static constexpr int THREADS = 256;
static constexpr int STAGES = 3;
static constexpr int B_OFF       = 16384;
static constexpr int STAGE_BYTES = 32768;
static constexpr int SMEM_TOTAL  = 1024 + STAGES * STAGE_BYTES;  // 99328/CTA

__global__ __launch_bounds__(THREADS, 2)
void ffn_fused_kernel(const float* __restrict__ x,
                      const float* __restrict__ gamma,
                      const float* __restrict__ beta,
                      const float* __restrict__ W,
                      const float* __restrict__ bias,
                      float* __restrict__ out,
                      int K, int H, int wBlocks) {
    const int b = blockIdx.x;
    const int t = threadIdx.x;

    // =========== phase A: W transpose -> fp16 (blocks [0, wBlocks)) ===========
    if (b < wBlocks) {
        __shared__ float tile[32][33];
        const int n0 = (b & (H / 32 - 1)) * 32;
        const int k0 = (b / (H / 32)) * 32;
        const int tx = t & 31, ty = t >> 5;  // 32 x 8
        #pragma unroll
        for (int r = 0; r < 32; r += 8)
            tile[ty + r][tx] = W[(size_t)(k0 + ty + r) * H + n0 + tx];
        __syncthreads();
        #pragma unroll
        for (int r = 0; r < 32; r += 8) {
            const int n = n0 + ty + r, k = k0 + tx;
            g_B[(size_t)n * K + k] = __float2half(tile[tx][ty + r]);
        }
        __threadfence();
        __syncthreads();
        if (t == 0) atomicAdd(&g_flags[256 + (n0 >> 7)], 1);
        return;
    }

    const int c     = b - wBlocks;
    const int chunk = c >> 5;     // row-block 0..255
    const int pos   = c & 31;

    // =========== phase B: LayerNorm (16 blocks per row-block) ===========
    if (pos < 16) {
        const int lb   = chunk * 16 + pos;     // LN block: rows lb*8 .. lb*8+7
        const int wid  = t >> 5;
        const int lane = t & 31;
        const int row  = lb * 8 + wid;
        const float* xr = x + (size_t)row * K;

        float4 v[16];
        #pragma unroll
        for (int i = 0; i < 16; i++)
            v[i] = *reinterpret_cast<const float4*>(xr + (i * 32 + lane) * 4);

        float s = 0.f, s2 = 0.f;
        #pragma unroll
        for (int i = 0; i < 16; i++) {
            s  += v[i].x + v[i].y + v[i].z + v[i].w;
            s2 += v[i].x * v[i].x + v[i].y * v[i].y
                + v[i].z * v[i].z + v[i].w * v[i].w;
        }
        #pragma unroll
        for (int o = 16; o > 0; o >>= 1) {
            s  += __shfl_xor_sync(0xFFFFFFFFu, s, o);
            s2 += __shfl_xor_sync(0xFFFFFFFFu, s2, o);
        }
        const float mu = s / (float)K;
        const float rs = rsqrtf(s2 / (float)K - mu * mu + LN_EPS);

        __half* arow = g_A + (size_t)row * K;
        #pragma unroll
        for (int i = 0; i < 16; i++) {
            const int cc = (i * 32 + lane) * 4;
            const float4 g4 = *reinterpret_cast<const float4*>(gamma + cc);
            const float4 b4 = *reinterpret_cast<const float4*>(beta  + cc);
            union { __half h[4]; uint2 u; } o;
            o.h[0] = __float2half((v[i].x - mu) * rs * g4.x + b4.x);
            o.h[1] = __float2half((v[i].y - mu) * rs * g4.y + b4.y);
            o.h[2] = __float2half((v[i].z - mu) * rs * g4.z + b4.z);
            o.h[3] = __float2half((v[i].w - mu) * rs * g4.w + b4.w);
            *reinterpret_cast<uint2*>(arow + cc) = o.u;
        }
        __threadfence();
        __syncthreads();
        if (t == 0) atomicAdd(&g_flags[chunk], 1);
        return;
    }

    // =========== phase C: GEMM tile (by=chunk, bx=pos-16) ===========
    const int by = chunk, bx = pos - 16;

    if (t == 0) {
        while (atomicAdd(&g_flags[256 + bx], 0) < (K / 32) * 4) __nanosleep(64);
        while (atomicAdd(&g_flags[by], 0) < 16) __nanosleep(64);
    }
    __syncthreads();

    extern __shared__ __align__(1024) uint8_t dynsmem[];
    uint32_t sb = smem_u32(dynsmem);
    sb = (sb + 1023) & ~1023u;

    const int lane = t & 31;
    const int wid  = t >> 5;
    const int g    = lane >> 2;
    const int tg   = lane & 3;
    const int m0   = by * BM;
    const int n0   = bx * BN;
    const int wm   = (wid >> 2) * 64;
    const int wn   = (wid & 3)  * 32;

    const int ldrow = t >> 3;
    const int ldc   = t & 7;
    const size_t aoff = (size_t)(m0 + ldrow) * K + ldc * 8;
    const size_t boff = (size_t)(n0 + ldrow) * K + ldc * 8;
    const __half* pA = g_A + aoff;
    const __half* pB = g_B + boff;
    const size_t rstep = (size_t)32 * K;

    const uint32_t dstA = sb + swz((uint32_t)(ldrow * 128 + ldc * 16));
    const uint32_t dstB = sb + B_OFF + swz((uint32_t)(ldrow * 128 + ldc * 16));

    const int matid = lane >> 3, r8 = lane & 7;
    uint32_t aAdr[4], bAdr[2];
    #pragma unroll
    for (int mt = 0; mt < 4; mt++) {
        const uint32_t m = wm + mt * 16 + (matid & 1) * 8 + r8;
        aAdr[mt] = sb + swz(m * 128 + (matid >> 1) * 16);
    }
    #pragma unroll
    for (int p = 0; p < 2; p++) {
        const uint32_t n = wn + p * 16 + (matid >> 1) * 8 + r8;
        bAdr[p] = sb + B_OFF + swz(n * 128 + (matid & 1) * 16);
    }

    float acc[4][4][4];
    #pragma unroll
    for (int mt = 0; mt < 4; mt++)
        #pragma unroll
        for (int nt = 0; nt < 4; nt++)
            #pragma unroll
            for (int r = 0; r < 4; r++) acc[mt][nt][r] = 0.f;

    const int NT = K / BK;   // 32

    auto load_stage = [&](int kt, uint32_t so) {
        const int kc = kt * BK;
        const __half* a = pA + kc;
        const __half* bb = pB + kc;
        #pragma unroll
        for (int i = 0; i < 4; i++) {
            cp16(dstA + so + i * 4096, a + i * rstep);
            cp16(dstB + so + i * 4096, bb + i * rstep);
        }
    };

    load_stage(0, 0);
    asm volatile("cp.async.commit_group;" ::: "memory");
    load_stage(1, STAGE_BYTES);
    asm volatile("cp.async.commit_group;" ::: "memory");

    int cur = 0, nxt2 = 2;

    for (int kt = 0; kt < NT; kt++) {
        asm volatile("cp.async.wait_group 1;" ::: "memory");
        __syncthreads();

        if (kt + 2 < NT) load_stage(kt + 2, nxt2 * STAGE_BYTES);
        asm volatile("cp.async.commit_group;" ::: "memory");

        const uint32_t so = cur * STAGE_BYTES;

        #pragma unroll
        for (int ks = 0; ks < 4; ks++) {
            const uint32_t kx = ks * 32;
            uint32_t bh[8];
            #pragma unroll
            for (int p = 0; p < 2; p++)
                ldsm4(&bh[p * 4], (bAdr[p] + so) ^ kx);
            uint32_t ah[4][4];
            #pragma unroll
            for (int mt = 0; mt < 4; mt++)
                ldsm4(ah[mt], (aAdr[mt] + so) ^ kx);
            #pragma unroll
            for (int mt = 0; mt < 4; mt++)
                #pragma unroll
                for (int nt = 0; nt < 4; nt++)
                    mma16816(acc[mt][nt], ah[mt], &bh[nt * 2]);
        }

        cur  = (cur  == 2) ? 0 : cur  + 1;
        nxt2 = (nxt2 == 2) ? 0 : nxt2 + 1;
    }

    // ---- epilogue: bias + exact GELU + residual ----
    #pragma unroll
    for (int mt = 0; mt < 4; mt++) {
        #pragma unroll
        for (int half = 0; half < 2; half++) {
            const int m = m0 + wm + mt * 16 + g + half * 8;
            const float* xr = x + (size_t)m * H;
            float* orow = out + (size_t)m * H;
            #pragma unroll
            for (int nt = 0; nt < 4; nt++) {
                const int n = n0 + wn + nt * 8 + tg * 2;
                float c0 = acc[mt][nt][half * 2 + 0];
                float c1 = acc[mt][nt][half * 2 + 1];
                const float2 bb = *reinterpret_cast<const float2*>(bias + n);
                float h0 = c0 + bb.x, h1 = c1 + bb.y;
                h0 = 0.5f * h0 * (1.0f + erff(h0 * 0.70710678118654752f));
                h1 = 0.5f * h1 * (1.0f + erff(h1 * 0.70710678118654752f));
                const float2 xv = *reinterpret_cast<const float2*>(xr + n);
                float2 o;
                o.x = h0 + xv.x;
                o.y = h1 + xv.y;
                *reinterpret_cast<float2*>(orow + n) = o;
            }
        }
    }
}

// ------------------------- host side ---------------------------------
extern "C" void kernel_launch(void* const* d_in, const int* in_sizes, int n_in,
                              void* d_out, int out_size) {
    const float* x     = (const float*)d_in[0];
    const float* gamma = (const float*)d_in[1];
    const float* beta  = (const float*)d_in[2];
    const float* W     = (const float*)d_in[3];
    const float* bias  = (const float*)d_in[4];
    float* out = (float*)d_out;

    const int D = in_sizes[1];
    const int H = in_sizes[4];
    const int M = in_sizes[0] / D;

    zero_flags_kernel<<<1, 272>>>();

    const int wBlocks  = (D / 32) * (H / 32);        // 4096
    const int rowBlks  = M / BM;                      // 256
    const int grid     = wBlocks + rowBlks * 32;      // 16 LN + 16 GEMM per row-block

    cudaFuncSetAttribute(ffn_fused_kernel,
                         cudaFuncAttributeMaxDynamicSharedMemorySize, SMEM_TOTAL);
    ffn_fused_kernel<<<grid, THREADS, SMEM_TOTAL>>>(x, gamma, beta, W, bias, out,
                                                    D, H, wBlocks);
}

// round 17
// speedup vs baseline: 1.1156x; 1.0432x over previous
#include <cuda_runtime.h>
#include <cuda_fp16.h>
#include <cstdint>

// =====================================================================
// Fused LayerNorm -> Linear -> exact GELU -> residual
//   x [M=32768, D=2048] fp32, W [D, H=2048] fp32, out [M, H] fp32
// R16: best-of composition. Merged prep launch (LN warp-per-row +
//      W-transpose, both DRAM-bound) + the R11 GEMM verbatim
//      (BM=BN=128, occ=2, 3-stage cp.async, tensor ~64% = HMMA ceiling).
//   D = A_fp16 * B_fp16 (fp32 accumulate), rel_err ~1.7e-4.
// =====================================================================

#define LN_EPS 1e-5f
static constexpr int MROWS = 32768;
static constexpr int DDIM  = 2048;

__device__ __align__(1024) __half g_A[(size_t)MROWS * DDIM];   // LN(x) fp16
__device__ __align__(1024) __half g_B[(size_t)DDIM * DDIM];    // W^T fp16 [N,K]

// ------------------------- helpers ----------------------------------
__device__ __forceinline__ uint32_t smem_u32(const void* p) {
    uint32_t a;
    asm("{ .reg .u64 t; cvta.to.shared.u64 t, %1; cvt.u32.u64 %0, t; }"
        : "=r"(a) : "l"(p));
    return a;
}
__device__ __forceinline__ uint32_t swz(uint32_t off) {   // SW128: bits[6:4] ^= bits[9:7]
    return off ^ ((off >> 3) & 0x70u);
}
__device__ __forceinline__ void cp16(uint32_t dst, const void* src) {
    asm volatile("cp.async.cg.shared.global [%0], [%1], 16;" :: "r"(dst), "l"(src));
}
__device__ __forceinline__ void ldsm4(uint32_t* r, uint32_t a) {
    asm volatile("ldmatrix.sync.aligned.m8n8.x4.shared.b16 {%0,%1,%2,%3}, [%4];"
        : "=r"(r[0]), "=r"(r[1]), "=r"(r[2]), "=r"(r[3]) : "r"(a));
}
__device__ __forceinline__ void mma16816(float* c, const uint32_t* a, const uint32_t* b) {
    asm volatile(
        "mma.sync.aligned.m16n8k16.row.col.f32.f16.f16.f32 "
        "{%0,%1,%2,%3}, {%4,%5,%6,%7}, {%8,%9}, {%0,%1,%2,%3};"
        : "+f"(c[0]), "+f"(c[1]), "+f"(c[2]), "+f"(c[3])
        : "r"(a[0]), "r"(a[1]), "r"(a[2]), "r"(a[3]), "r"(b[0]), "r"(b[1]));
}

// --------- Stage 1+2 merged: LN (warp/row) and W transpose ----------
__global__ __launch_bounds__(256)
void prep_kernel(const float* __restrict__ x,
                 const float* __restrict__ gamma,
                 const float* __restrict__ beta,
                 const float* __restrict__ W,
                 int D, int N, int lnBlocks) {
    if (blockIdx.x < (unsigned)lnBlocks) {
        const int wid  = threadIdx.x >> 5;
        const int lane = threadIdx.x & 31;
        const int row  = blockIdx.x * 8 + wid;
        const float* xr = x + (size_t)row * D;

        float4 v[16];
        #pragma unroll
        for (int i = 0; i < 16; i++)
            v[i] = *reinterpret_cast<const float4*>(xr + (i * 32 + lane) * 4);

        float s = 0.f, s2 = 0.f;
        #pragma unroll
        for (int i = 0; i < 16; i++) {
            s  += v[i].x + v[i].y + v[i].z + v[i].w;
            s2 += v[i].x * v[i].x + v[i].y * v[i].y
                + v[i].z * v[i].z + v[i].w * v[i].w;
        }
        #pragma unroll
        for (int o = 16; o > 0; o >>= 1) {
            s  += __shfl_xor_sync(0xFFFFFFFFu, s, o);
            s2 += __shfl_xor_sync(0xFFFFFFFFu, s2, o);
        }
        const float mu = s / (float)D;
        const float rs = rsqrtf(s2 / (float)D - mu * mu + LN_EPS);

        __half* arow = g_A + (size_t)row * D;
        #pragma unroll
        for (int i = 0; i < 16; i++) {
            const int c = (i * 32 + lane) * 4;
            const float4 g4 = *reinterpret_cast<const float4*>(gamma + c);
            const float4 b4 = *reinterpret_cast<const float4*>(beta  + c);
            union { __half h[4]; uint2 u; } o;
            o.h[0] = __float2half((v[i].x - mu) * rs * g4.x + b4.x);
            o.h[1] = __float2half((v[i].y - mu) * rs * g4.y + b4.y);
            o.h[2] = __float2half((v[i].z - mu) * rs * g4.z + b4.z);
            o.h[3] = __float2half((v[i].w - mu) * rs * g4.w + b4.w);
            *reinterpret_cast<uint2*>(arow + c) = o.u;
        }
    } else {
        __shared__ float tile[32][33];
        const int b  = blockIdx.x - lnBlocks;
        const int n0 = (b & (N / 32 - 1)) * 32;
        const int k0 = (b / (N / 32)) * 32;
        const int tx = threadIdx.x & 31, ty = threadIdx.x >> 5;  // 32 x 8
        #pragma unroll
        for (int r = 0; r < 32; r += 8)
            tile[ty + r][tx] = W[(size_t)(k0 + ty + r) * N + n0 + tx];
        __syncthreads();
        #pragma unroll
        for (int r = 0; r < 32; r += 8) {
            const int n = n0 + ty + r, k = k0 + tx;
            g_B[(size_t)n * D + k] = __float2half(tile[tx][ty + r]);
        }
    }
}

// ------------------------- Stage 3: GEMM (R11 verbatim) -------------
static constexpr int BM = 128, BN = 128, BK = 64;
static constexpr int THREADS = 256;
static constexpr int STAGES = 3;
// per-stage (128B rows): A [0,16K) B [16K,32K)
static constexpr int B_OFF       = 16384;
static constexpr int STAGE_BYTES = 32768;
static constexpr int SMEM_TOTAL  = 1024 + STAGES * STAGE_BYTES;  // 99328/CTA

__global__ __launch_bounds__(THREADS, 2)
void ffn_mma_kernel(const float* __restrict__ x,
                    const float* __restrict__ bias,
                    float* __restrict__ out,
                    int K, int H) {
    extern __shared__ __align__(1024) uint8_t dynsmem[];
    uint32_t sb = smem_u32(dynsmem);
    sb = (sb + 1023) & ~1023u;

    const int t    = threadIdx.x;
    const int lane = t & 31;
    const int wid  = t >> 5;
    const int g    = lane >> 2;
    const int tg   = lane & 3;
    const int m0   = blockIdx.y * BM;
    const int n0   = blockIdx.x * BN;
    const int wm   = (wid >> 2) * 64;   // 0 or 64
    const int wn   = (wid & 3)  * 32;   // 0..96

    // ---- cp.async: 128B rows, 8 x 16B chunks/row; 4 A + 4 B per thread
    const int ldrow = t >> 3;
    const int ldc   = t & 7;
    const size_t aoff = (size_t)(m0 + ldrow) * K + ldc * 8;
    const size_t boff = (size_t)(n0 + ldrow) * K + ldc * 8;
    const __half* pA = g_A + aoff;
    const __half* pB = g_B + boff;
    const size_t rstep = (size_t)32 * K;

    const uint32_t dstA = sb + swz((uint32_t)(ldrow * 128 + ldc * 16));
    const uint32_t dstB = sb + B_OFF + swz((uint32_t)(ldrow * 128 + ldc * 16));

    // ---- ldmatrix base addresses (stage 0, ks=0) ----
    const int matid = lane >> 3, r8 = lane & 7;
    uint32_t aAdr[4], bAdr[2];
    #pragma unroll
    for (int mt = 0; mt < 4; mt++) {
        const uint32_t m = wm + mt * 16 + (matid & 1) * 8 + r8;
        aAdr[mt] = sb + swz(m * 128 + (matid >> 1) * 16);
    }
    #pragma unroll
    for (int p = 0; p < 2; p++) {
        const uint32_t n = wn + p * 16 + (matid >> 1) * 8 + r8;
        bAdr[p] = sb + B_OFF + swz(n * 128 + (matid & 1) * 16);
    }

    float acc[4][4][4];
    #pragma unroll
    for (int mt = 0; mt < 4; mt++)
        #pragma unroll
        for (int nt = 0; nt < 4; nt++)
            #pragma unroll
            for (int r = 0; r < 4; r++) acc[mt][nt][r] = 0.f;

    const int NT = K / BK;   // 32

    auto load_stage = [&](int kt, uint32_t so) {
        const int kc = kt * BK;
        const __half* a = pA + kc;
        const __half* b = pB + kc;
        #pragma unroll
        for (int i = 0; i < 4; i++) {
            cp16(dstA + so + i * 4096, a + i * rstep);
            cp16(dstB + so + i * 4096, b + i * rstep);
        }
    };

    load_stage(0, 0);
    asm volatile("cp.async.commit_group;" ::: "memory");
    load_stage(1, STAGE_BYTES);
    asm volatile("cp.async.commit_group;" ::: "memory");

    int cur = 0, nxt2 = 2;

    for (int kt = 0; kt < NT; kt++) {
        asm volatile("cp.async.wait_group 1;" ::: "memory");
        __syncthreads();

        if (kt + 2 < NT) load_stage(kt + 2, nxt2 * STAGE_BYTES);
        asm volatile("cp.async.commit_group;" ::: "memory");

        const uint32_t so = cur * STAGE_BYTES;

        #pragma unroll
        for (int ks = 0; ks < 4; ks++) {
            const uint32_t kx = ks * 32;   // XOR step, swizzle-transparent
            uint32_t bh[8];
            #pragma unroll
            for (int p = 0; p < 2; p++)
                ldsm4(&bh[p * 4], (bAdr[p] + so) ^ kx);
            uint32_t ah[4][4];
            #pragma unroll
            for (int mt = 0; mt < 4; mt++)
                ldsm4(ah[mt], (aAdr[mt] + so) ^ kx);
            #pragma unroll
            for (int mt = 0; mt < 4; mt++)
                #pragma unroll
                for (int nt = 0; nt < 4; nt++)
                    mma16816(acc[mt][nt], ah[mt], &bh[nt * 2]);
        }

        cur  = (cur  == 2) ? 0 : cur  + 1;
        nxt2 = (nxt2 == 2) ? 0 : nxt2 + 1;
    }

    // ---- epilogue: bias + exact GELU + residual ----
    #pragma unroll
    for (int mt = 0; mt < 4; mt++) {
        #pragma unroll
        for (int half = 0; half < 2; half++) {
            const int m = m0 + wm + mt * 16 + g + half * 8;
            const float* xr = x + (size_t)m * H;
            float* orow = out + (size_t)m * H;
            #pragma unroll
            for (int nt = 0; nt < 4; nt++) {
                const int n = n0 + wn + nt * 8 + tg * 2;
                float c0 = acc[mt][nt][half * 2 + 0];
                float c1 = acc[mt][nt][half * 2 + 1];
                const float2 bb = *reinterpret_cast<const float2*>(bias + n);
                float h0 = c0 + bb.x, h1 = c1 + bb.y;
                h0 = 0.5f * h0 * (1.0f + erff(h0 * 0.70710678118654752f));
                h1 = 0.5f * h1 * (1.0f + erff(h1 * 0.70710678118654752f));
                const float2 xv = *reinterpret_cast<const float2*>(xr + n);
                float2 o;
                o.x = h0 + xv.x;
                o.y = h1 + xv.y;
                *reinterpret_cast<float2*>(orow + n) = o;
            }
        }
    }
}

// ------------------------- host side ---------------------------------
extern "C" void kernel_launch(void* const* d_in, const int* in_sizes, int n_in,
                              void* d_out, int out_size) {
    const float* x     = (const float*)d_in[0];
    const float* gamma = (const float*)d_in[1];
    const float* beta  = (const float*)d_in[2];
    const float* W     = (const float*)d_in[3];
    const float* bias  = (const float*)d_in[4];
    float* out = (float*)d_out;

    const int D = in_sizes[1];
    const int H = in_sizes[4];
    const int M = in_sizes[0] / D;

    const int lnBlocks = M / 8;
    const int wBlocks  = (D / 32) * (H / 32);
    prep_kernel<<<lnBlocks + wBlocks, 256>>>(x, gamma, beta, W, D, H, lnBlocks);

    cudaFuncSetAttribute(ffn_mma_kernel,
                         cudaFuncAttributeMaxDynamicSharedMemorySize, SMEM_TOTAL);
    dim3 ggrid(H / BN, M / BM);
    ffn_mma_kernel<<<ggrid, THREADS, SMEM_TOTAL>>>(x, bias, out, D, H);
}